// round 2
// baseline (speedup 1.0000x reference)
#include <cuda_runtime.h>
#include <cuda_bf16.h>
#include <math.h>

// Problem constants: x [B=32, C=64, H=128, W=128] -> N = 16384 per (b,c)
#define BB 32
#define CC 64
#define NN 16384

// Scratch (device globals; no allocation allowed)
__device__ float g_sigma;
__device__ float g_gram[BB * CC * CC];   // per-batch Gram xxT
__device__ float g_Amat[BB * CC * CC];   // A_b = gamma * gram_b @ Wsn + I

// ---------------------------------------------------------------------------
// Kernel 0: zero the Gram accumulators (replaces cudaMemsetAsync — pure
// kernel launch, unambiguously graph-capturable on any capture stream).
// ---------------------------------------------------------------------------
__global__ void zero_gram_kernel()
{
    int i = blockIdx.x * blockDim.x + threadIdx.x;
    // BB*CC*CC = 131072 floats; grid covers exactly.
    g_gram[i] = 0.f;
}

// ---------------------------------------------------------------------------
// Kernel 1: spectral-norm power iteration.
//   v = normalize(W^T u); sigma = ||W v||  (== u2 @ (W v) in the reference)
// One block, 64 threads.
// ---------------------------------------------------------------------------
__global__ void prep_kernel(const float* __restrict__ W, const float* __restrict__ u)
{
    __shared__ float sh[CC];
    __shared__ float svec[CC];
    int t = threadIdx.x;  // 0..63

    // t-th component of W^T u
    float acc = 0.f;
    #pragma unroll 8
    for (int r = 0; r < CC; r++) acc += W[r * CC + t] * u[r];

    sh[t] = acc * acc;
    __syncthreads();
    for (int s = 32; s > 0; s >>= 1) { if (t < s) sh[t] += sh[t + s]; __syncthreads(); }
    float nt = sqrtf(sh[0]);
    __syncthreads();

    float v = acc / fmaxf(nt, 1e-12f);
    svec[t] = v;
    __syncthreads();

    float w = 0.f;
    #pragma unroll 8
    for (int c = 0; c < CC; c++) w += W[t * CC + c] * svec[c];

    sh[t] = w * w;
    __syncthreads();
    for (int s = 32; s > 0; s >>= 1) { if (t < s) sh[t] += sh[t + s]; __syncthreads(); }
    if (t == 0) {
        float nw2 = sh[0];
        float nw  = sqrtf(nw2);
        g_sigma = nw2 / fmaxf(nw, 1e-12f);  // == sigma = u2 @ (W v)
    }
}

// ---------------------------------------------------------------------------
// Kernel 2: Gram matrices.  g_gram[b] += x[b] @ x[b]^T over this block's
// 512-column chunk of N.  64 threads, 8x8 register tile each (64x64 output).
// grid = (32 chunks, 32 batches)
// ---------------------------------------------------------------------------
__global__ __launch_bounds__(64) void gram_kernel(const float* __restrict__ x)
{
    __shared__ float xs[64][68];  // [k within tile][channel], padded vs conflicts
    const int b  = blockIdx.y;
    const int n0 = blockIdx.x * 512;
    const int t  = threadIdx.x;
    const int r0 = (t >> 3) * 8;
    const int c0 = (t & 7) * 8;
    const float* xb = x + (size_t)b * CC * NN;

    float acc[8][8];
    #pragma unroll
    for (int i = 0; i < 8; i++)
        #pragma unroll
        for (int j = 0; j < 8; j++) acc[i][j] = 0.f;

    for (int kt = 0; kt < 8; ++kt) {
        // Load 64x64 tile, transpose into xs[k][c]. Thread t owns channel t.
        const float4* src = (const float4*)(xb + (size_t)t * NN + n0 + kt * 64);
        #pragma unroll
        for (int q = 0; q < 16; q++) {
            float4 vq = src[q];
            xs[q * 4 + 0][t] = vq.x;
            xs[q * 4 + 1][t] = vq.y;
            xs[q * 4 + 2][t] = vq.z;
            xs[q * 4 + 3][t] = vq.w;
        }
        __syncthreads();

        #pragma unroll 8
        for (int k = 0; k < 64; k++) {
            float4 a0 = *(const float4*)&xs[k][r0];
            float4 a1 = *(const float4*)&xs[k][r0 + 4];
            float4 b0 = *(const float4*)&xs[k][c0];
            float4 b1 = *(const float4*)&xs[k][c0 + 4];
            float av[8] = {a0.x, a0.y, a0.z, a0.w, a1.x, a1.y, a1.z, a1.w};
            float bv[8] = {b0.x, b0.y, b0.z, b0.w, b1.x, b1.y, b1.z, b1.w};
            #pragma unroll
            for (int i = 0; i < 8; i++)
                #pragma unroll
                for (int j = 0; j < 8; j++)
                    acc[i][j] = fmaf(av[i], bv[j], acc[i][j]);
        }
        __syncthreads();
    }

    float* gb = g_gram + b * CC * CC;
    #pragma unroll
    for (int i = 0; i < 8; i++)
        #pragma unroll
        for (int j = 0; j < 8; j++)
            atomicAdd(&gb[(r0 + i) * CC + (c0 + j)], acc[i][j]);
}

// ---------------------------------------------------------------------------
// Kernel 3: A_b = gamma * gram_b @ (W / sigma) + I     (tiny: 32 blocks x 64)
// ---------------------------------------------------------------------------
__global__ __launch_bounds__(64) void makeA_kernel(const float* __restrict__ W,
                                                   const float* __restrict__ gamma)
{
    __shared__ float sW[CC * CC];
    const int b = blockIdx.x;
    const int t = threadIdx.x;

    const float inv_sigma = 1.f / g_sigma;
    for (int i = t; i < CC * CC; i += 64) sW[i] = W[i] * inv_sigma;
    __syncthreads();

    const float g = gamma[0];
    const float* gr = g_gram + b * CC * CC + t * CC;
    float grl[CC];
    #pragma unroll
    for (int d = 0; d < CC; d++) grl[d] = gr[d];

    float* Ar = g_Amat + b * CC * CC + t * CC;
    for (int e = 0; e < CC; e++) {
        float acc = 0.f;
        #pragma unroll 16
        for (int d = 0; d < CC; d++) acc = fmaf(grl[d], sW[d * CC + e], acc);
        Ar[e] = g * acc + ((t == e) ? 1.f : 0.f);
    }
}

// ---------------------------------------------------------------------------
// Kernel 4: out[b] = A_b @ x[b]   (identity inside A_b provides the +xf)
// 64 threads, 8x8 tile; each block handles 4 tiles of 64 columns (256 cols).
// grid = (64 chunks, 32 batches)
// ---------------------------------------------------------------------------
__global__ __launch_bounds__(64) void apply_kernel(const float* __restrict__ x,
                                                   float* __restrict__ out)
{
    __shared__ float Ast[64][68];  // A transposed: Ast[k][r] = A[r][k]
    __shared__ float xs[64][68];   // xs[k][n_local]
    const int b  = blockIdx.y;
    const int n0 = blockIdx.x * 256;
    const int t  = threadIdx.x;
    const int r0 = (t >> 3) * 8;
    const int c0 = (t & 7) * 8;

    // Load A_b transposed (thread t owns row t of A)
    const float4* Asrc = (const float4*)(g_Amat + (size_t)b * CC * CC + t * CC);
    #pragma unroll
    for (int q = 0; q < 16; q++) {
        float4 vq = Asrc[q];
        Ast[q * 4 + 0][t] = vq.x;
        Ast[q * 4 + 1][t] = vq.y;
        Ast[q * 4 + 2][t] = vq.z;
        Ast[q * 4 + 3][t] = vq.w;
    }

    const float* xb = x   + (size_t)b * CC * NN;
    float*       ob = out + (size_t)b * CC * NN;

    for (int tile = 0; tile < 4; ++tile) {
        const int nb = n0 + tile * 64;
        __syncthreads();  // Ast visible (1st iter) / xs consumers done (later)

        // Thread t loads input-channel row t: contiguous, vectorized.
        const float4* src = (const float4*)(xb + (size_t)t * NN + nb);
        #pragma unroll
        for (int q = 0; q < 16; q++)
            *(float4*)&xs[t][q * 4] = src[q];
        __syncthreads();

        float acc[8][8];
        #pragma unroll
        for (int i = 0; i < 8; i++)
            #pragma unroll
            for (int j = 0; j < 8; j++) acc[i][j] = 0.f;

        #pragma unroll 8
        for (int k = 0; k < 64; k++) {
            float4 a0 = *(const float4*)&Ast[k][r0];
            float4 a1 = *(const float4*)&Ast[k][r0 + 4];
            float4 b0 = *(const float4*)&xs[k][c0];
            float4 b1 = *(const float4*)&xs[k][c0 + 4];
            float av[8] = {a0.x, a0.y, a0.z, a0.w, a1.x, a1.y, a1.z, a1.w};
            float bv[8] = {b0.x, b0.y, b0.z, b0.w, b1.x, b1.y, b1.z, b1.w};
            #pragma unroll
            for (int i = 0; i < 8; i++)
                #pragma unroll
                for (int j = 0; j < 8; j++)
                    acc[i][j] = fmaf(av[i], bv[j], acc[i][j]);
        }

        #pragma unroll
        for (int i = 0; i < 8; i++) {
            float4 o0 = {acc[i][0], acc[i][1], acc[i][2], acc[i][3]};
            float4 o1 = {acc[i][4], acc[i][5], acc[i][6], acc[i][7]};
            *(float4*)(ob + (size_t)(r0 + i) * NN + nb + c0)     = o0;
            *(float4*)(ob + (size_t)(r0 + i) * NN + nb + c0 + 4) = o1;
        }
    }
}

// ---------------------------------------------------------------------------
// Launch — kernel launches only (graph-capture safe on any stream).
// ---------------------------------------------------------------------------
extern "C" void kernel_launch(void* const* d_in, const int* in_sizes, int n_in,
                              void* d_out, int out_size)
{
    // Map inputs defensively by element count (all four are distinct).
    const float* x = nullptr;     // 32*64*16384
    const float* W = nullptr;     // 4096
    const float* gamma = nullptr; // 1
    const float* u = nullptr;     // 64
    for (int i = 0; i < n_in; i++) {
        if (in_sizes[i] == BB * CC * NN) x = (const float*)d_in[i];
        else if (in_sizes[i] == CC * CC) W = (const float*)d_in[i];
        else if (in_sizes[i] == CC)      u = (const float*)d_in[i];
        else if (in_sizes[i] == 1)       gamma = (const float*)d_in[i];
    }
    float* out = (float*)d_out;

    zero_gram_kernel<<<(BB * CC * CC) / 256, 256>>>();
    prep_kernel<<<1, 64>>>(W, u);
    gram_kernel<<<dim3(32, BB), 64>>>(x);
    makeA_kernel<<<BB, 64>>>(W, gamma);
    apply_kernel<<<dim3(64, BB), 64>>>(x, out);
}

// round 16
// speedup vs baseline: 1.1625x; 1.1625x over previous
#include <cuda_runtime.h>
#include <cuda_bf16.h>
#include <math.h>

// Problem constants: x [B=32, C=64, H=128, W=128] -> N = 16384 per (b,c)
#define BB 32
#define CC 64
#define NN 16384

typedef unsigned long long ull;

// Packed f32x2 helpers (Blackwell sm_100+: fma.rn.f32x2 -> FFMA2, same fma pipe)
__device__ __forceinline__ ull dup2(float a) {
    ull r; asm("mov.b64 %0, {%1,%1};" : "=l"(r) : "f"(a)); return r;
}
__device__ __forceinline__ void fma2(ull& d, ull a, ull b) {
    asm("fma.rn.f32x2 %0, %1, %2, %0;" : "+l"(d) : "l"(a), "l"(b));
}
__device__ __forceinline__ float2 unpk(ull p) {
    float2 f; asm("mov.b64 {%0,%1}, %2;" : "=f"(f.x), "=f"(f.y) : "l"(p)); return f;
}

// Scratch (device globals; no allocation allowed)
__device__ float g_sigma;
__device__ float g_gram[BB * CC * CC];   // per-batch Gram xxT
__device__ float g_Amat[BB * CC * CC];   // A_b = gamma * gram_b @ Wsn + I

// ---------------------------------------------------------------------------
// Kernel 0: zero the Gram accumulators.
// ---------------------------------------------------------------------------
__global__ void zero_gram_kernel()
{
    int i = blockIdx.x * blockDim.x + threadIdx.x;
    g_gram[i] = 0.f;
}

// ---------------------------------------------------------------------------
// Kernel 1: spectral norm: v = normalize(W^T u); sigma = ||W v||.
// ---------------------------------------------------------------------------
__global__ void prep_kernel(const float* __restrict__ W, const float* __restrict__ u)
{
    __shared__ float sh[CC];
    __shared__ float svec[CC];
    int t = threadIdx.x;  // 0..63

    float acc = 0.f;
    #pragma unroll 8
    for (int r = 0; r < CC; r++) acc += W[r * CC + t] * u[r];

    sh[t] = acc * acc;
    __syncthreads();
    for (int s = 32; s > 0; s >>= 1) { if (t < s) sh[t] += sh[t + s]; __syncthreads(); }
    float nt = sqrtf(sh[0]);
    __syncthreads();

    svec[t] = acc / fmaxf(nt, 1e-12f);
    __syncthreads();

    float w = 0.f;
    #pragma unroll 8
    for (int c = 0; c < CC; c++) w += W[t * CC + c] * svec[c];

    sh[t] = w * w;
    __syncthreads();
    for (int s = 32; s > 0; s >>= 1) { if (t < s) sh[t] += sh[t + s]; __syncthreads(); }
    if (t == 0) {
        float nw2 = sh[0];
        float nw  = sqrtf(nw2);
        g_sigma = nw2 / fmaxf(nw, 1e-12f);
    }
}

// ---------------------------------------------------------------------------
// Kernel 2: Gram.  g_gram[b] += x[b] @ x[b]^T over a 512-col chunk of N.
// 64 threads, 8x8 output per thread via packed f32x2 FMA (8x4 pairs).
// grid = (32 chunks, 32 batches)
// ---------------------------------------------------------------------------
__global__ __launch_bounds__(64) void gram_kernel(const float* __restrict__ x)
{
    __shared__ float xs[64][68];  // [k][channel], padded
    const int b  = blockIdx.y;
    const int n0 = blockIdx.x * 512;
    const int t  = threadIdx.x;
    const int r0 = (t >> 3) * 8;
    const int c0 = (t & 7) * 8;
    const float* xb = x + (size_t)b * CC * NN;

    ull acc2[8][4];
    #pragma unroll
    for (int i = 0; i < 8; i++)
        #pragma unroll
        for (int j = 0; j < 4; j++) acc2[i][j] = 0ull;  // bit pattern of (0.f,0.f)

    for (int kt = 0; kt < 8; ++kt) {
        const float4* src = (const float4*)(xb + (size_t)t * NN + n0 + kt * 64);
        #pragma unroll
        for (int q = 0; q < 16; q++) {
            float4 vq = src[q];
            xs[q * 4 + 0][t] = vq.x;
            xs[q * 4 + 1][t] = vq.y;
            xs[q * 4 + 2][t] = vq.z;
            xs[q * 4 + 3][t] = vq.w;
        }
        __syncthreads();

        #pragma unroll 4
        for (int k = 0; k < 64; k++) {
            float4 a0 = *(const float4*)&xs[k][r0];
            float4 a1 = *(const float4*)&xs[k][r0 + 4];
            ull a2[8];
            a2[0] = dup2(a0.x); a2[1] = dup2(a0.y); a2[2] = dup2(a0.z); a2[3] = dup2(a0.w);
            a2[4] = dup2(a1.x); a2[5] = dup2(a1.y); a2[6] = dup2(a1.z); a2[7] = dup2(a1.w);
            ull b2[4];
            b2[0] = *(const ull*)&xs[k][c0];
            b2[1] = *(const ull*)&xs[k][c0 + 2];
            b2[2] = *(const ull*)&xs[k][c0 + 4];
            b2[3] = *(const ull*)&xs[k][c0 + 6];
            #pragma unroll
            for (int i = 0; i < 8; i++)
                #pragma unroll
                for (int j = 0; j < 4; j++)
                    fma2(acc2[i][j], a2[i], b2[j]);
        }
        __syncthreads();
    }

    float* gb = g_gram + b * CC * CC;
    #pragma unroll
    for (int i = 0; i < 8; i++)
        #pragma unroll
        for (int j = 0; j < 4; j++) {
            float2 v = unpk(acc2[i][j]);
            atomicAdd(&gb[(r0 + i) * CC + c0 + 2 * j],     v.x);
            atomicAdd(&gb[(r0 + i) * CC + c0 + 2 * j + 1], v.y);
        }
}

// ---------------------------------------------------------------------------
// Kernel 3: A_b = gamma * gram_b @ (W / sigma) + I
// 256 threads/block, one block per batch. Thread t: row r = t>>2,
// 16 consecutive output columns starting at (t&3)*16.
// ---------------------------------------------------------------------------
__global__ __launch_bounds__(256) void makeA_kernel(const float* __restrict__ W,
                                                    const float* __restrict__ gamma)
{
    __shared__ float sW[CC][68];  // sW[d][e] = W[d][e]/sigma, padded
    __shared__ float sG[CC][65];  // sG[r][d] = gram_b[r][d],  padded
    const int b = blockIdx.x;
    const int t = threadIdx.x;

    const float inv_sigma = 1.f / g_sigma;
    const float* gb = g_gram + b * CC * CC;
    for (int i = t; i < CC * CC; i += 256) {
        sW[i >> 6][i & 63] = W[i] * inv_sigma;
        sG[i >> 6][i & 63] = gb[i];
    }
    __syncthreads();

    const int r  = t >> 2;
    const int e0 = (t & 3) * 16;
    const float g = gamma[0];

    float acc[16];
    #pragma unroll
    for (int j = 0; j < 16; j++) acc[j] = 0.f;

    #pragma unroll 4
    for (int d = 0; d < CC; d++) {
        float gv = sG[r][d];
        float4 w0 = *(const float4*)&sW[d][e0];
        float4 w1 = *(const float4*)&sW[d][e0 + 4];
        float4 w2 = *(const float4*)&sW[d][e0 + 8];
        float4 w3 = *(const float4*)&sW[d][e0 + 12];
        acc[0]  = fmaf(gv, w0.x, acc[0]);  acc[1]  = fmaf(gv, w0.y, acc[1]);
        acc[2]  = fmaf(gv, w0.z, acc[2]);  acc[3]  = fmaf(gv, w0.w, acc[3]);
        acc[4]  = fmaf(gv, w1.x, acc[4]);  acc[5]  = fmaf(gv, w1.y, acc[5]);
        acc[6]  = fmaf(gv, w1.z, acc[6]);  acc[7]  = fmaf(gv, w1.w, acc[7]);
        acc[8]  = fmaf(gv, w2.x, acc[8]);  acc[9]  = fmaf(gv, w2.y, acc[9]);
        acc[10] = fmaf(gv, w2.z, acc[10]); acc[11] = fmaf(gv, w2.w, acc[11]);
        acc[12] = fmaf(gv, w3.x, acc[12]); acc[13] = fmaf(gv, w3.y, acc[13]);
        acc[14] = fmaf(gv, w3.z, acc[14]); acc[15] = fmaf(gv, w3.w, acc[15]);
    }

    float* Ar = g_Amat + b * CC * CC + r * CC + e0;
    #pragma unroll
    for (int j = 0; j < 16; j++)
        Ar[j] = g * acc[j] + ((r == e0 + j) ? 1.f : 0.f);
}

// ---------------------------------------------------------------------------
// Kernel 4: out[b] = A_b @ x[b]   (identity inside A_b provides +xf)
// 64 threads, 8x8 per thread via packed f32x2; 4 tiles of 64 cols per block.
// grid = (64 chunks, 32 batches)
// ---------------------------------------------------------------------------
__global__ __launch_bounds__(64) void apply_kernel(const float* __restrict__ x,
                                                   float* __restrict__ out)
{
    __shared__ float Ast[64][68];  // Ast[k][r] = A[r][k]
    __shared__ float xs[64][68];   // xs[k][n_local]
    const int b  = blockIdx.y;
    const int n0 = blockIdx.x * 256;
    const int t  = threadIdx.x;
    const int r0 = (t >> 3) * 8;
    const int c0 = (t & 7) * 8;

    const float4* Asrc = (const float4*)(g_Amat + (size_t)b * CC * CC + t * CC);
    #pragma unroll
    for (int q = 0; q < 16; q++) {
        float4 vq = Asrc[q];
        Ast[q * 4 + 0][t] = vq.x;
        Ast[q * 4 + 1][t] = vq.y;
        Ast[q * 4 + 2][t] = vq.z;
        Ast[q * 4 + 3][t] = vq.w;
    }

    const float* xb = x   + (size_t)b * CC * NN;
    float*       ob = out + (size_t)b * CC * NN;

    for (int tile = 0; tile < 4; ++tile) {
        const int nb = n0 + tile * 64;
        __syncthreads();  // Ast visible (1st iter) / xs consumers done (later)

        const float4* src = (const float4*)(xb + (size_t)t * NN + nb);
        #pragma unroll
        for (int q = 0; q < 16; q++)
            *(float4*)&xs[t][q * 4] = src[q];
        __syncthreads();

        ull acc2[8][4];
        #pragma unroll
        for (int i = 0; i < 8; i++)
            #pragma unroll
            for (int j = 0; j < 4; j++) acc2[i][j] = 0ull;

        #pragma unroll 4
        for (int k = 0; k < 64; k++) {
            float4 a0 = *(const float4*)&Ast[k][r0];
            float4 a1 = *(const float4*)&Ast[k][r0 + 4];
            ull a2[8];
            a2[0] = dup2(a0.x); a2[1] = dup2(a0.y); a2[2] = dup2(a0.z); a2[3] = dup2(a0.w);
            a2[4] = dup2(a1.x); a2[5] = dup2(a1.y); a2[6] = dup2(a1.z); a2[7] = dup2(a1.w);
            ull b2[4];
            b2[0] = *(const ull*)&xs[k][c0];
            b2[1] = *(const ull*)&xs[k][c0 + 2];
            b2[2] = *(const ull*)&xs[k][c0 + 4];
            b2[3] = *(const ull*)&xs[k][c0 + 6];
            #pragma unroll
            for (int i = 0; i < 8; i++)
                #pragma unroll
                for (int j = 0; j < 4; j++)
                    fma2(acc2[i][j], a2[i], b2[j]);
        }

        #pragma unroll
        for (int i = 0; i < 8; i++) {
            float2 p0 = unpk(acc2[i][0]);
            float2 p1 = unpk(acc2[i][1]);
            float2 p2 = unpk(acc2[i][2]);
            float2 p3 = unpk(acc2[i][3]);
            float4 o0 = {p0.x, p0.y, p1.x, p1.y};
            float4 o1 = {p2.x, p2.y, p3.x, p3.y};
            *(float4*)(ob + (size_t)(r0 + i) * NN + nb + c0)     = o0;
            *(float4*)(ob + (size_t)(r0 + i) * NN + nb + c0 + 4) = o1;
        }
    }
}

// ---------------------------------------------------------------------------
// Launch — kernel launches only (graph-capture safe on any stream).
// ---------------------------------------------------------------------------
extern "C" void kernel_launch(void* const* d_in, const int* in_sizes, int n_in,
                              void* d_out, int out_size)
{
    const float* x = nullptr;     // 32*64*16384
    const float* W = nullptr;     // 4096
    const float* gamma = nullptr; // 1
    const float* u = nullptr;     // 64
    for (int i = 0; i < n_in; i++) {
        if (in_sizes[i] == BB * CC * NN) x = (const float*)d_in[i];
        else if (in_sizes[i] == CC * CC) W = (const float*)d_in[i];
        else if (in_sizes[i] == CC)      u = (const float*)d_in[i];
        else if (in_sizes[i] == 1)       gamma = (const float*)d_in[i];
    }
    float* out = (float*)d_out;

    zero_gram_kernel<<<(BB * CC * CC) / 256, 256>>>();
    prep_kernel<<<1, 64>>>(W, u);
    gram_kernel<<<dim3(32, BB), 64>>>(x);
    makeA_kernel<<<BB, 256>>>(W, gamma);
    apply_kernel<<<dim3(64, BB), 64>>>(x, out);
}